// round 1
// baseline (speedup 1.0000x reference)
#include <cuda_runtime.h>
#include <cstdint>

#define XDIM 1024
#define KDIM 64
#define IT 32
#define NCHUNK (XDIM / IT)
#define ROWS_PER_CTA 128
#define THREADS 128

// smem stage layout (floats)
#define XS_STRIDE 33                       // pad 1 -> conflict-free x LDS
#define XS_FLOATS (ROWS_PER_CTA * XS_STRIDE)   // 4224
#define VS_ROW    68                       // two 32-float halves at byte offsets 0 and 144
#define VS_FLOATS (IT * VS_ROW)            // 2176
#define WP_FLOATS (IT * 2)                 // 64
#define STAGE_FLOATS (XS_FLOATS + VS_FLOATS + WP_FLOATS)   // 6464
#define SMEM_BYTES (2 * STAGE_FLOATS * 4)  // 51712

__device__ float g_wp[XDIM * 2];   // wp[i][kg] = sum_{k in kg*32..+32} v[i][k]^2

__device__ __forceinline__ unsigned smaddr(const void* p) {
    return (unsigned)__cvta_generic_to_shared(p);
}

__device__ __forceinline__ void cp4(unsigned dst, const void* src) {
    asm volatile("cp.async.ca.shared.global [%0], [%1], 4;" :: "r"(dst), "l"(src));
}
__device__ __forceinline__ void cp16(unsigned dst, const void* src) {
    asm volatile("cp.async.cg.shared.global [%0], [%1], 16;" :: "r"(dst), "l"(src));
}

__device__ __forceinline__ unsigned long long bcast2(float x) {
    unsigned long long r;
    asm("mov.b64 %0, {%1, %1};" : "=l"(r) : "f"(x));
    return r;
}
__device__ __forceinline__ void fma2(unsigned long long& d, unsigned long long a,
                                     unsigned long long b) {
    // d = a * b + d, lanewise f32x2
    asm volatile("fma.rn.f32x2 %0, %1, %2, %0;" : "+l"(d) : "l"(a), "l"(b));
}

__global__ void prep_kernel(const float* __restrict__ v) {
    int i = blockIdx.x * blockDim.x + threadIdx.x;
    if (i < XDIM) {
        float s0 = 0.f, s1 = 0.f;
        #pragma unroll 8
        for (int k = 0; k < 32; k++) { float a = v[i * KDIM + k];      s0 = fmaf(a, a, s0); }
        #pragma unroll 8
        for (int k = 32; k < 64; k++) { float a = v[i * KDIM + k];     s1 = fmaf(a, a, s1); }
        g_wp[2 * i + 0] = s0;
        g_wp[2 * i + 1] = s1;
    }
}

__global__ __launch_bounds__(THREADS, 1)
void fm_main(const float* __restrict__ x, const float* __restrict__ v,
             float* __restrict__ out) {
    extern __shared__ float smem[];
    const int tid = threadIdx.x;
    const int kg = tid & 1;          // k-group: k in [kg*32, kg*32+32)
    const int rg = tid >> 1;         // row-group: rows 2*rg, 2*rg+1
    const int row0 = blockIdx.x * ROWS_PER_CTA;

    unsigned long long a0[16], a1[16];   // 32 f32x2 accumulators = 64 y values
    #pragma unroll
    for (int j = 0; j < 16; j++) { a0[j] = 0ull; a1[j] = 0ull; }
    float q0 = 0.f, q1 = 0.f;            // partial sum_of_square (per kg slice)

    auto load_chunk = [&](int c, int s) {
        float* xs  = smem + s * STAGE_FLOATS;
        float* vs  = xs + XS_FLOATS;
        float* wps = vs + VS_FLOATS;
        const int i0 = c * IT;
        // x tile: 128 rows x 32 cols = 4096 words, 32 cp.async.4 per thread
        #pragma unroll
        for (int n = 0; n < 32; n++) {
            int w = tid + n * THREADS;
            int r = w >> 5, col = w & 31;
            cp4(smaddr(xs + r * XS_STRIDE + col),
                x + (size_t)(row0 + r) * XDIM + i0 + col);
        }
        // v tile: 32 rows x 64 cols = 512 16B chunks, split-half smem layout
        #pragma unroll
        for (int n = 0; n < 4; n++) {
            int g = tid + n * THREADS;
            int i = g >> 4, h = (g >> 3) & 1, off = g & 7;
            cp16(smaddr(vs) + i * 272 + h * 144 + off * 16,
                 v + (size_t)(i0 + i) * KDIM + h * 32 + off * 4);
        }
        // wp tile: 64 floats = 16 chunks
        if (tid < 16) {
            cp16(smaddr(wps) + tid * 16, g_wp + i0 * 2 + tid * 4);
        }
        asm volatile("cp.async.commit_group;");
    };

    auto compute_chunk = [&](int s) {
        const float* xs  = smem + s * STAGE_FLOATS;
        const float* vs  = xs + XS_FLOATS;
        const float* wps = vs + VS_FLOATS;
        const float* xr0 = xs + (2 * rg) * XS_STRIDE;
        const float* xr1 = xr0 + XS_STRIDE;
        const char*  vb  = (const char*)vs + kg * 144;
        #pragma unroll 4
        for (int i = 0; i < IT; i++) {
            float x0 = xr0[i], x1 = xr1[i];
            float wq = wps[i * 2 + kg];
            q0 = fmaf(x0 * x0, wq, q0);
            q1 = fmaf(x1 * x1, wq, q1);
            unsigned long long xx0 = bcast2(x0);
            unsigned long long xx1 = bcast2(x1);
            const ulonglong2* vp = (const ulonglong2*)(vb + i * 272);
            #pragma unroll
            for (int j = 0; j < 8; j++) {
                ulonglong2 vv = vp[j];
                fma2(a0[2 * j + 0], vv.x, xx0);
                fma2(a0[2 * j + 1], vv.y, xx0);
                fma2(a1[2 * j + 0], vv.x, xx1);
                fma2(a1[2 * j + 1], vv.y, xx1);
            }
        }
    };

    load_chunk(0, 0);
    for (int c = 0; c < NCHUNK; c++) {
        if (c + 1 < NCHUNK) {
            load_chunk(c + 1, (c + 1) & 1);
            asm volatile("cp.async.wait_group 1;");
        } else {
            asm volatile("cp.async.wait_group 0;");
        }
        __syncthreads();
        compute_chunk(c & 1);
        __syncthreads();
    }

    // epilogue: sum y^2 over this thread's 32 k's, subtract q, reduce kg pair
    float s0 = 0.f, s1 = 0.f;
    #pragma unroll
    for (int j = 0; j < 16; j++) {
        float lo = __uint_as_float((unsigned)(a0[j] & 0xffffffffull));
        float hi = __uint_as_float((unsigned)(a0[j] >> 32));
        s0 = fmaf(lo, lo, s0);
        s0 = fmaf(hi, hi, s0);
        lo = __uint_as_float((unsigned)(a1[j] & 0xffffffffull));
        hi = __uint_as_float((unsigned)(a1[j] >> 32));
        s1 = fmaf(lo, lo, s1);
        s1 = fmaf(hi, hi, s1);
    }
    float t0 = s0 - q0;
    float t1 = s1 - q1;
    t0 += __shfl_xor_sync(0xffffffffu, t0, 1);
    t1 += __shfl_xor_sync(0xffffffffu, t1, 1);
    if (kg == 0) {
        out[row0 + 2 * rg + 0] = 0.5f * t0;
        out[row0 + 2 * rg + 1] = 0.5f * t1;
    }
}

extern "C" void kernel_launch(void* const* d_in, const int* in_sizes, int n_in,
                              void* d_out, int out_size) {
    const float* x = (const float*)d_in[0];
    const float* v = (const float*)d_in[1];
    float* out = (float*)d_out;
    const int B = in_sizes[0] / XDIM;   // 16384

    prep_kernel<<<(XDIM + 255) / 256, 256>>>(v);

    cudaFuncSetAttribute(fm_main, cudaFuncAttributeMaxDynamicSharedMemorySize,
                         SMEM_BYTES);
    fm_main<<<B / ROWS_PER_CTA, THREADS, SMEM_BYTES>>>(x, v, out);
}